// round 10
// baseline (speedup 1.0000x reference)
#include <cuda_runtime.h>
#include <cuda_bf16.h>
#include <cstdint>

#define B_ 8
#define T_ 256
#define H_ 1024
#define V_ 32000
#define M_ (B_*T_)          // 2048 rows = (b,t)

// ---------------- scratch (device globals; no allocation allowed) ----------
__device__ __align__(16) __nv_bfloat16 g_Ahi[M_*H_];           // emb hi
__device__ __align__(16) __nv_bfloat16 g_Alo[M_*H_];           // emb lo
__device__ __align__(16) __nv_bfloat16 g_Wih_hi[H_*H_];
__device__ __align__(16) __nv_bfloat16 g_Wih_lo[H_*H_];
__device__ __align__(16) __nv_bfloat16 g_Wo_hi[(size_t)V_*H_];
__device__ __align__(16) __nv_bfloat16 g_Wo_lo[(size_t)V_*H_];
__device__ __align__(16) __nv_bfloat16 g_Hhi[M_*H_];           // hs hi
__device__ __align__(16) __nv_bfloat16 g_Hlo[M_*H_];           // hs lo
__device__ __align__(16) float g_pre[M_*H_];   // x_t @ W_ih^T + b_ih + b_hh
__device__ __align__(16) float g_hs [M_*H_];   // hidden states [b][t][j]
__device__ __align__(16) float g_h  [2*B_*H_]; // double-buffered current h
__device__ float g_bsum[H_];
__device__ unsigned g_bar_count;
__device__ unsigned g_bar_gen;

// ---------------- PTX helpers (arch-neutral: ldmatrix/mma/cp.async) --------
__device__ __forceinline__ uint32_t smem_to_u32(const void* p) {
    uint32_t a;
    asm("{ .reg .u64 t; cvta.to.shared.u64 t, %1; cvt.u32.u64 %0, t; }"
        : "=r"(a) : "l"(p));
    return a;
}
__device__ __forceinline__ void ldsm_x4(uint32_t* r, uint32_t addr) {
    asm volatile("ldmatrix.sync.aligned.m8n8.x4.shared.b16 {%0,%1,%2,%3}, [%4];"
        : "=r"(r[0]), "=r"(r[1]), "=r"(r[2]), "=r"(r[3]) : "r"(addr));
}
__device__ __forceinline__ void mma_bf16(float* d, const uint32_t* a, const uint32_t* b) {
    asm volatile(
        "mma.sync.aligned.m16n8k16.row.col.f32.bf16.bf16.f32 "
        "{%0,%1,%2,%3}, {%4,%5,%6,%7}, {%8,%9}, {%0,%1,%2,%3};"
        : "+f"(d[0]), "+f"(d[1]), "+f"(d[2]), "+f"(d[3])
        : "r"(a[0]), "r"(a[1]), "r"(a[2]), "r"(a[3]), "r"(b[0]), "r"(b[1]));
}
__device__ __forceinline__ void cp16(uint32_t saddr, const void* g) {
    asm volatile("cp.async.cg.shared.global [%0], [%1], 16;" :: "r"(saddr), "l"(g));
}
#define CP_COMMIT() asm volatile("cp.async.commit_group;" ::: "memory")
#define CP_WAIT0()  asm volatile("cp.async.wait_group 0;" ::: "memory")
#define CP_WAIT1()  asm volatile("cp.async.wait_group 1;" ::: "memory")

// ---------------- gather: emb rows split to bf16 hi/lo + fused bias --------
__global__ void gather_kernel(const int* __restrict__ x,
                              const float* __restrict__ embed,
                              const float* __restrict__ b_ih,
                              const float* __restrict__ b_hh) {
    int m = blockIdx.x;
    if (m < M_) {
        int tok = x[m];
        for (int i = threadIdx.x; i < H_; i += blockDim.x) {
            float v = embed[(size_t)tok * H_ + i];
            __nv_bfloat16 h = __float2bfloat16(v);
            g_Ahi[(size_t)m * H_ + i] = h;
            g_Alo[(size_t)m * H_ + i] = __float2bfloat16(v - __bfloat162float(h));
        }
    } else {
        for (int i = threadIdx.x; i < H_; i += blockDim.x)
            g_bsum[i] = b_ih[i] + b_hh[i];
    }
}

// ---------------- fp32 -> bf16 hi/lo split ---------------------------------
__global__ void split_kernel(const float* __restrict__ src,
                             __nv_bfloat16* __restrict__ hi,
                             __nv_bfloat16* __restrict__ lo, size_t n) {
    size_t i = ((size_t)blockIdx.x * blockDim.x + threadIdx.x) * 4;
    if (i < n) {
        float4 v = *reinterpret_cast<const float4*>(src + i);
        __nv_bfloat16 h0 = __float2bfloat16(v.x), h1 = __float2bfloat16(v.y);
        __nv_bfloat16 h2 = __float2bfloat16(v.z), h3 = __float2bfloat16(v.w);
        __nv_bfloat162 hh0 = {h0, h1}, hh1 = {h2, h3};
        __nv_bfloat162 ll0 = {__float2bfloat16(v.x - __bfloat162float(h0)),
                              __float2bfloat16(v.y - __bfloat162float(h1))};
        __nv_bfloat162 ll1 = {__float2bfloat16(v.z - __bfloat162float(h2)),
                              __float2bfloat16(v.w - __bfloat162float(h3))};
        *reinterpret_cast<__nv_bfloat162*>(hi + i)     = hh0;
        *reinterpret_cast<__nv_bfloat162*>(hi + i + 2) = hh1;
        *reinterpret_cast<__nv_bfloat162*>(lo + i)     = ll0;
        *reinterpret_cast<__nv_bfloat162*>(lo + i + 2) = ll1;
    }
}

// ---------------- split-bf16 HMMA GEMM (256x128 tile, 512 threads) ---------
// C[r][c] = sum_k A[r][k]*B[c][k] + bias[c] via Ahi*Bhi + Alo*Bhi + Ahi*Blo.
// A: [Mrows][H_] row-major, B: [Ncols][H_] row-major.  K = H_ = 1024 fixed.
#define GBM 256
#define GBN 128
#define GBK 32
#define NKC (H_/GBK)                    // 32 k-chunks
#define LDT 40                          // smem row stride in bf16 (pad 8)
#define MAT_A (GBM*LDT*2)               // 20480 bytes per A matrix tile
#define MAT_Bt (GBN*LDT*2)              // 10240 bytes per B matrix tile
#define OFF_AHI 0
#define OFF_ALO MAT_A
#define OFF_BHI (2*MAT_A)
#define OFF_BLO (2*MAT_A + MAT_Bt)
#define STAGE_B (2*MAT_A + 2*MAT_Bt)    // 61440 bytes per stage
#define SMEM_B (2*STAGE_B)              // 122880 bytes total

__global__ __launch_bounds__(512, 1)
void gemm_mma(const __nv_bfloat16* __restrict__ Ahi, const __nv_bfloat16* __restrict__ Alo,
              const __nv_bfloat16* __restrict__ Bhi, const __nv_bfloat16* __restrict__ Blo,
              const float* __restrict__ bias, float* __restrict__ C, int Ndim) {
    extern __shared__ __align__(16) char sm[];
    const uint32_t sb = smem_to_u32(sm);
    const int tid  = threadIdx.x;
    const int lane = tid & 31, wid = tid >> 5;   // 16 warps
    const int wm = wid & 7, wn = wid >> 3;       // warp tile: rows 32*wm, cols 64*wn
    const int bm = blockIdx.x, bn = blockIdx.y;

    // ---- prefetch chunk c into stage c&1 (6 x cp.async.16B per thread) ----
    auto prefetch = [&](int c) {
        const uint32_t st = sb + (uint32_t)(c & 1) * STAGE_B;
        const int kcol = c * GBK;
        // A tiles: 256 rows x 4 segs = 1024 slots over 512 threads
        #pragma unroll
        for (int q = 0; q < 2; q++) {
            const int u = tid + 512*q;
            const int r = u >> 2, sg = u & 3;
            const uint32_t so = (uint32_t)(r*LDT + sg*8) * 2;
            const size_t goA = (size_t)(bm*GBM + r) * H_ + kcol + sg*8;
            cp16(st + OFF_AHI + so, Ahi + goA);
            cp16(st + OFF_ALO + so, Alo + goA);
        }
        // B tiles: 128 rows x 4 segs = 512 slots
        {
            const int r = tid >> 2, sg = tid & 3;
            const uint32_t so = (uint32_t)(r*LDT + sg*8) * 2;
            const size_t goB = (size_t)(bn*GBN + r) * H_ + kcol + sg*8;
            cp16(st + OFF_BHI + so, Bhi + goB);
            cp16(st + OFF_BLO + so, Blo + goB);
        }
    };

    float acc[2][8][4];
    #pragma unroll
    for (int i = 0; i < 2; i++)
        #pragma unroll
        for (int j = 0; j < 8; j++)
            #pragma unroll
            for (int q = 0; q < 4; q++) acc[i][j][q] = 0.f;

    prefetch(0); CP_COMMIT();

    for (int c = 0; c < NKC; c++) {
        if (c + 1 < NKC) { prefetch(c + 1); CP_COMMIT(); CP_WAIT1(); }
        else             { CP_WAIT0(); }
        __syncthreads();

        const uint32_t st = sb + (uint32_t)(c & 1) * STAGE_B;
        #pragma unroll
        for (int ks = 0; ks < 2; ks++) {
            // A fragments (hi & lo): rows wm*32 + f*16 + lane%16
            uint32_t ah[8], al[8];
            #pragma unroll
            for (int f = 0; f < 2; f++) {
                const int row = wm*32 + f*16 + (lane & 15);
                const uint32_t off = (uint32_t)(row*LDT + ks*16 + (lane >> 4)*8) * 2;
                ldsm_x4(ah + 4*f, st + OFF_AHI + off);
                ldsm_x4(al + 4*f, st + OFF_ALO + off);
            }
            // B-fragment smem offsets (shared by hi and lo tiles)
            uint32_t boff[4];
            #pragma unroll
            for (int p = 0; p < 4; p++) {
                const int n  = wn*64 + p*16 + ((lane >> 4) << 3) + (lane & 7);
                const int kc = ks*16 + ((lane >> 3) & 1) * 8;
                boff[p] = (uint32_t)(n*LDT + kc) * 2;
            }
            uint32_t bb[16];
            // ---- load Bhi fragments ----
            #pragma unroll
            for (int p = 0; p < 4; p++) ldsm_x4(bb + 4*p, st + OFF_BHI + boff[p]);
            // pass 1: Ahi * Bhi
            #pragma unroll
            for (int fm = 0; fm < 2; fm++)
                #pragma unroll
                for (int fn = 0; fn < 8; fn++)
                    mma_bf16(acc[fm][fn], ah + 4*fm, bb + 2*fn);
            // pass 2: Alo * Bhi
            #pragma unroll
            for (int fm = 0; fm < 2; fm++)
                #pragma unroll
                for (int fn = 0; fn < 8; fn++)
                    mma_bf16(acc[fm][fn], al + 4*fm, bb + 2*fn);
            // ---- overwrite with Blo fragments ----
            #pragma unroll
            for (int p = 0; p < 4; p++) ldsm_x4(bb + 4*p, st + OFF_BLO + boff[p]);
            // pass 3: Ahi * Blo
            #pragma unroll
            for (int fm = 0; fm < 2; fm++)
                #pragma unroll
                for (int fn = 0; fn < 8; fn++)
                    mma_bf16(acc[fm][fn], ah + 4*fm, bb + 2*fn);
        }
        __syncthreads();
    }

    // ---- epilogue: acc + bias -> C ----
    #pragma unroll
    for (int fm = 0; fm < 2; fm++) {
        const int row = bm*GBM + wm*32 + fm*16 + (lane >> 2);
        #pragma unroll
        for (int fn = 0; fn < 8; fn++) {
            const int col = bn*GBN + wn*64 + fn*8 + (lane & 3)*2;
            const float2 bv = *reinterpret_cast<const float2*>(bias + col);
            float2 o0, o1;
            o0.x = acc[fm][fn][0] + bv.x; o0.y = acc[fm][fn][1] + bv.y;
            o1.x = acc[fm][fn][2] + bv.x; o1.y = acc[fm][fn][3] + bv.y;
            *reinterpret_cast<float2*>(C + (size_t)row     * Ndim + col) = o0;
            *reinterpret_cast<float2*>(C + (size_t)(row+8) * Ndim + col) = o1;
        }
    }
}

// ---------------- persistent scan kernel (R6 config: 128 x 256) ------------
#define SCAN_BLOCKS 128

__device__ __forceinline__ void grid_barrier(int nb) {
    __syncthreads();
    if (threadIdx.x == 0) {
        unsigned g = *((volatile unsigned*)&g_bar_gen);
        __threadfence();
        if (atomicAdd(&g_bar_count, 1) == (unsigned)(nb - 1)) {
            g_bar_count = 0;
            __threadfence();
            *((volatile unsigned*)&g_bar_gen) = g + 1;
        } else {
            while (*((volatile unsigned*)&g_bar_gen) == g) { __nanosleep(32); }
        }
        __threadfence();
    }
    __syncthreads();
}

__global__ __launch_bounds__(256)
void scan_kernel(const float* __restrict__ Whh, float* __restrict__ hfinal) {
    __shared__ __align__(16) float hsh[B_*H_];   // 32 KB
    const int tid  = threadIdx.x;
    const int warp = tid >> 5;
    const int lane = tid & 31;
    const int j    = blockIdx.x * 8 + warp;      // one output column per warp

    float4 w[8];
    const float4* wrow = reinterpret_cast<const float4*>(Whh + (size_t)j * H_);
    #pragma unroll
    for (int i = 0; i < 8; i++) w[i] = wrow[lane + 32*i];

    for (int idx = blockIdx.x*256 + tid; idx < B_*H_; idx += SCAN_BLOCKS*256)
        g_h[idx] = 0.f;
    grid_barrier(SCAN_BLOCKS);

    for (int t = 0; t < T_; t++) {
        const int rp = t & 1, wp = rp ^ 1;
        float4* hs4 = reinterpret_cast<float4*>(hsh);
        const float4* hg4 = reinterpret_cast<const float4*>(g_h + rp*B_*H_);
        #pragma unroll
        for (int i = 0; i < (B_*H_/4)/256; i++) hs4[tid + 256*i] = hg4[tid + 256*i];
        __syncthreads();

        float acc[B_];
        #pragma unroll
        for (int b = 0; b < B_; b++) acc[b] = 0.f;
        #pragma unroll
        for (int i = 0; i < 8; i++) {
            const float4 wv = w[i];
            #pragma unroll
            for (int b = 0; b < B_; b++) {
                const float4 hv = *reinterpret_cast<const float4*>(&hsh[b*H_ + lane*4 + 128*i]);
                acc[b] += wv.x*hv.x + wv.y*hv.y + wv.z*hv.z + wv.w*hv.w;
            }
        }
        #pragma unroll
        for (int b = 0; b < B_; b++) {
            #pragma unroll
            for (int off = 16; off; off >>= 1)
                acc[b] += __shfl_xor_sync(0xffffffffu, acc[b], off);
        }
        if (lane < B_) {
            float a = acc[0];
            if (lane == 1) a = acc[1];
            if (lane == 2) a = acc[2];
            if (lane == 3) a = acc[3];
            if (lane == 4) a = acc[4];
            if (lane == 5) a = acc[5];
            if (lane == 6) a = acc[6];
            if (lane == 7) a = acc[7];
            const float hn = tanhf(a + g_pre[(size_t)lane*(T_*H_) + t*H_ + j]);
            g_h[wp*B_*H_ + lane*H_ + j] = hn;
            g_hs[(size_t)lane*(T_*H_) + t*H_ + j] = hn;
            if (t == T_-1) hfinal[lane*H_ + j] = hn;
        }
        __threadfence();
        grid_barrier(SCAN_BLOCKS);
    }
}

// ---------------- launch ----------------------------------------------------
extern "C" void kernel_launch(void* const* d_in, const int* in_sizes, int n_in,
                              void* d_out, int out_size) {
    const int*   x     = (const int*)  d_in[0];
    const float* embed = (const float*)d_in[1];
    const float* W_ih  = (const float*)d_in[2];
    const float* b_ih  = (const float*)d_in[3];
    const float* W_hh  = (const float*)d_in[4];
    const float* b_hh  = (const float*)d_in[5];
    const float* W_out = (const float*)d_in[6];
    const float* b_out = (const float*)d_in[7];
    float* out = (float*)d_out;

    void *p_Ahi, *p_Alo, *p_Wih_hi, *p_Wih_lo, *p_Wo_hi, *p_Wo_lo;
    void *p_Hhi, *p_Hlo, *p_pre, *p_hs, *p_bsum;
    cudaGetSymbolAddress(&p_Ahi, g_Ahi);       cudaGetSymbolAddress(&p_Alo, g_Alo);
    cudaGetSymbolAddress(&p_Wih_hi, g_Wih_hi); cudaGetSymbolAddress(&p_Wih_lo, g_Wih_lo);
    cudaGetSymbolAddress(&p_Wo_hi, g_Wo_hi);   cudaGetSymbolAddress(&p_Wo_lo, g_Wo_lo);
    cudaGetSymbolAddress(&p_Hhi, g_Hhi);       cudaGetSymbolAddress(&p_Hlo, g_Hlo);
    cudaGetSymbolAddress(&p_pre, g_pre);       cudaGetSymbolAddress(&p_hs, g_hs);
    cudaGetSymbolAddress(&p_bsum, g_bsum);

    cudaFuncSetAttribute(gemm_mma, cudaFuncAttributeMaxDynamicSharedMemorySize, SMEM_B);

    // 1) gather embeddings (split to bf16 hi/lo) + fused bias
    gather_kernel<<<M_ + 1, 256>>>(x, embed, b_ih, b_hh);

    // 2) split weights to bf16 hi/lo
    split_kernel<<<(H_*H_/4 + 255)/256, 256>>>(W_ih,
        (__nv_bfloat16*)p_Wih_hi, (__nv_bfloat16*)p_Wih_lo, (size_t)H_*H_);
    split_kernel<<<(int)(((size_t)V_*H_/4 + 255)/256), 256>>>(W_out,
        (__nv_bfloat16*)p_Wo_hi, (__nv_bfloat16*)p_Wo_lo, (size_t)V_*H_);

    // 3) pre = emb @ W_ih^T + (b_ih + b_hh)   [2048 x 1024]
    gemm_mma<<<dim3(M_/GBM, H_/GBN), 512, SMEM_B>>>(
        (const __nv_bfloat16*)p_Ahi, (const __nv_bfloat16*)p_Alo,
        (const __nv_bfloat16*)p_Wih_hi, (const __nv_bfloat16*)p_Wih_lo,
        (const float*)p_bsum, (float*)p_pre, H_);

    // 4) persistent recurrent scan; writes g_hs and h_final tail of d_out
    scan_kernel<<<SCAN_BLOCKS, 256>>>(W_hh, out + (size_t)M_ * V_);

    // 5) split hidden states to bf16 hi/lo
    split_kernel<<<(M_*H_/4 + 255)/256, 256>>>((const float*)p_hs,
        (__nv_bfloat16*)p_Hhi, (__nv_bfloat16*)p_Hlo, (size_t)M_*H_);

    // 6) outputs = hs @ W_out^T + b_out   [2048 x 32000]
    gemm_mma<<<dim3(M_/GBM, V_/GBN), 512, SMEM_B>>>(
        (const __nv_bfloat16*)p_Hhi, (const __nv_bfloat16*)p_Hlo,
        (const __nv_bfloat16*)p_Wo_hi, (const __nv_bfloat16*)p_Wo_lo,
        b_out, out, V_);
}

// round 11
// speedup vs baseline: 1.1672x; 1.1672x over previous
#include <cuda_runtime.h>
#include <cuda_bf16.h>
#include <cstdint>
#include <cstring>

#define B_ 8
#define T_ 256
#define H_ 1024
#define V_ 32000
#define M_ (B_*T_)          // 2048 rows = (b,t)

// ---------------- scratch (device globals; no allocation allowed) ----------
__device__ __align__(16) __nv_bfloat16 g_Ahi[M_*H_];           // emb hi
__device__ __align__(16) __nv_bfloat16 g_Alo[M_*H_];           // emb lo
__device__ __align__(16) __nv_bfloat16 g_Wih_hi[H_*H_];
__device__ __align__(16) __nv_bfloat16 g_Wih_lo[H_*H_];
__device__ __align__(16) __nv_bfloat16 g_Wo_hi[(size_t)V_*H_];
__device__ __align__(16) __nv_bfloat16 g_Wo_lo[(size_t)V_*H_];
__device__ __align__(16) __nv_bfloat16 g_Hhi[M_*H_];           // hs hi
__device__ __align__(16) __nv_bfloat16 g_Hlo[M_*H_];           // hs lo
__device__ __align__(16) float g_pre[M_*H_];   // x_t @ W_ih^T + b_ih + b_hh
__device__ __align__(16) float g_hs [M_*H_];   // hidden states [b][t][j]
__device__ __align__(16) float g_h  [2*B_*H_]; // double-buffered current h
__device__ float g_bsum[H_];
__device__ unsigned g_bar_count;
__device__ unsigned g_bar_gen;

// ---------------- PTX helpers (arch-neutral: ldmatrix/mma/cp.async) --------
__device__ __forceinline__ uint32_t smem_to_u32(const void* p) {
    uint32_t a;
    asm("{ .reg .u64 t; cvta.to.shared.u64 t, %1; cvt.u32.u64 %0, t; }"
        : "=r"(a) : "l"(p));
    return a;
}
__device__ __forceinline__ void ldsm_x4(uint32_t* r, uint32_t addr) {
    asm volatile("ldmatrix.sync.aligned.m8n8.x4.shared.b16 {%0,%1,%2,%3}, [%4];"
        : "=r"(r[0]), "=r"(r[1]), "=r"(r[2]), "=r"(r[3]) : "r"(addr));
}
__device__ __forceinline__ void mma_bf16(float* d, const uint32_t* a, const uint32_t* b) {
    asm volatile(
        "mma.sync.aligned.m16n8k16.row.col.f32.bf16.bf16.f32 "
        "{%0,%1,%2,%3}, {%4,%5,%6,%7}, {%8,%9}, {%0,%1,%2,%3};"
        : "+f"(d[0]), "+f"(d[1]), "+f"(d[2]), "+f"(d[3])
        : "r"(a[0]), "r"(a[1]), "r"(a[2]), "r"(a[3]), "r"(b[0]), "r"(b[1]));
}
__device__ __forceinline__ void cp16(uint32_t saddr, const void* g) {
    asm volatile("cp.async.cg.shared.global [%0], [%1], 16;" :: "r"(saddr), "l"(g));
}
#define CP_COMMIT() asm volatile("cp.async.commit_group;" ::: "memory")
#define CP_WAIT0()  asm volatile("cp.async.wait_group 0;" ::: "memory")
#define CP_WAIT1()  asm volatile("cp.async.wait_group 1;" ::: "memory")

// packed fp32x2 FMA (verified working in R2 on this toolchain)
__device__ __forceinline__ void ffma2(unsigned long long &c,
                                      unsigned long long a,
                                      unsigned long long b) {
    asm("fma.rn.f32x2 %0, %1, %2, %0;" : "+l"(c) : "l"(a), "l"(b));
}
__device__ __forceinline__ unsigned long long pk2(float x, float y) {
    float2 t; t.x = x; t.y = y;
    unsigned long long r; memcpy(&r, &t, 8); return r;
}
__device__ __forceinline__ float upk_sum(unsigned long long v) {
    float2 t; memcpy(&t, &v, 8); return t.x + t.y;
}

// ---------------- gather: emb rows split to bf16 hi/lo + fused bias --------
__global__ void gather_kernel(const int* __restrict__ x,
                              const float* __restrict__ embed,
                              const float* __restrict__ b_ih,
                              const float* __restrict__ b_hh) {
    int m = blockIdx.x;
    if (m < M_) {
        int tok = x[m];
        for (int i = threadIdx.x; i < H_; i += blockDim.x) {
            float v = embed[(size_t)tok * H_ + i];
            __nv_bfloat16 h = __float2bfloat16(v);
            g_Ahi[(size_t)m * H_ + i] = h;
            g_Alo[(size_t)m * H_ + i] = __float2bfloat16(v - __bfloat162float(h));
        }
    } else {
        for (int i = threadIdx.x; i < H_; i += blockDim.x)
            g_bsum[i] = b_ih[i] + b_hh[i];
    }
}

// ---------------- fp32 -> bf16 hi/lo split ---------------------------------
__global__ void split_kernel(const float* __restrict__ src,
                             __nv_bfloat16* __restrict__ hi,
                             __nv_bfloat16* __restrict__ lo, size_t n) {
    size_t i = ((size_t)blockIdx.x * blockDim.x + threadIdx.x) * 4;
    if (i < n) {
        float4 v = *reinterpret_cast<const float4*>(src + i);
        __nv_bfloat16 h0 = __float2bfloat16(v.x), h1 = __float2bfloat16(v.y);
        __nv_bfloat16 h2 = __float2bfloat16(v.z), h3 = __float2bfloat16(v.w);
        __nv_bfloat162 hh0 = {h0, h1}, hh1 = {h2, h3};
        __nv_bfloat162 ll0 = {__float2bfloat16(v.x - __bfloat162float(h0)),
                              __float2bfloat16(v.y - __bfloat162float(h1))};
        __nv_bfloat162 ll1 = {__float2bfloat16(v.z - __bfloat162float(h2)),
                              __float2bfloat16(v.w - __bfloat162float(h3))};
        *reinterpret_cast<__nv_bfloat162*>(hi + i)     = hh0;
        *reinterpret_cast<__nv_bfloat162*>(hi + i + 2) = hh1;
        *reinterpret_cast<__nv_bfloat162*>(lo + i)     = ll0;
        *reinterpret_cast<__nv_bfloat162*>(lo + i + 2) = ll1;
    }
}

// ---------------- split-bf16 HMMA GEMM (R9 best: 128x128, 2 CTA/SM) --------
// C[r][c] = sum_k A[r][k]*B[c][k] + bias[c] via Ahi*Bhi + Alo*Bhi + Ahi*Blo.
// A: [Mrows][H_] row-major, B: [Ncols][H_] row-major.  K = H_ = 1024 fixed.
#define GBM 128
#define GBN 128
#define GBK 32
#define NKC (H_/GBK)                    // 32 k-chunks
#define LDT 40                          // smem row stride in bf16 (pad 8)
#define MAT_B (GBM*LDT*2)               // 10240 bytes per matrix tile
#define STAGE_B (4*MAT_B)               // 40960 bytes per stage
#define SMEM_B (2*STAGE_B)              // 81920 bytes total

__global__ __launch_bounds__(256, 2)
void gemm_mma(const __nv_bfloat16* __restrict__ Ahi, const __nv_bfloat16* __restrict__ Alo,
              const __nv_bfloat16* __restrict__ Bhi, const __nv_bfloat16* __restrict__ Blo,
              const float* __restrict__ bias, float* __restrict__ C, int Ndim) {
    extern __shared__ __align__(16) char sm[];
    const uint32_t sb = smem_to_u32(sm);
    const int tid  = threadIdx.x;
    const int lane = tid & 31, wid = tid >> 5;
    const int wm = wid & 3, wn = wid >> 2;      // warp tile: rows 32*wm, cols 64*wn
    const int bm = blockIdx.x, bn = blockIdx.y;

    // ---- prefetch chunk c into stage c&1 (8 x cp.async.16B per thread) ----
    auto prefetch = [&](int c) {
        const uint32_t st = sb + (uint32_t)(c & 1) * STAGE_B;
        const int kcol = c * GBK;
        #pragma unroll
        for (int q = 0; q < 2; q++) {
            const int u = tid + 256*q;
            const int r = u >> 2, sg = u & 3;
            const uint32_t so = (uint32_t)(r*LDT + sg*8) * 2;
            const size_t goA = (size_t)(bm*GBM + r) * H_ + kcol + sg*8;
            const size_t goB = (size_t)(bn*GBN + r) * H_ + kcol + sg*8;
            cp16(st + 0*MAT_B + so, Ahi + goA);
            cp16(st + 1*MAT_B + so, Alo + goA);
            cp16(st + 2*MAT_B + so, Bhi + goB);
            cp16(st + 3*MAT_B + so, Blo + goB);
        }
    };

    float acc[2][8][4];
    #pragma unroll
    for (int i = 0; i < 2; i++)
        #pragma unroll
        for (int j = 0; j < 8; j++)
            #pragma unroll
            for (int q = 0; q < 4; q++) acc[i][j][q] = 0.f;

    prefetch(0); CP_COMMIT();

    for (int c = 0; c < NKC; c++) {
        if (c + 1 < NKC) { prefetch(c + 1); CP_COMMIT(); CP_WAIT1(); }
        else             { CP_WAIT0(); }
        __syncthreads();

        const uint32_t st = sb + (uint32_t)(c & 1) * STAGE_B;
        #pragma unroll
        for (int ks = 0; ks < 2; ks++) {
            // A fragments (hi & lo): rows wm*32 + f*16 + lane%16
            uint32_t ah[8], al[8];
            #pragma unroll
            for (int f = 0; f < 2; f++) {
                const int row = wm*32 + f*16 + (lane & 15);
                const uint32_t off = (uint32_t)(row*LDT + ks*16 + (lane >> 4)*8) * 2;
                ldsm_x4(ah + 4*f, st + 0*MAT_B + off);
                ldsm_x4(al + 4*f, st + 1*MAT_B + off);
            }
            // B-fragment smem offsets (shared by hi and lo tiles)
            uint32_t boff[4];
            #pragma unroll
            for (int p = 0; p < 4; p++) {
                const int n  = wn*64 + p*16 + ((lane >> 4) << 3) + (lane & 7);
                const int kc = ks*16 + ((lane >> 3) & 1) * 8;
                boff[p] = (uint32_t)(n*LDT + kc) * 2;
            }
            uint32_t bb[16];
            // ---- load Bhi fragments ----
            #pragma unroll
            for (int p = 0; p < 4; p++) ldsm_x4(bb + 4*p, st + 2*MAT_B + boff[p]);
            // pass 1: Ahi * Bhi
            #pragma unroll
            for (int fm = 0; fm < 2; fm++)
                #pragma unroll
                for (int fn = 0; fn < 8; fn++)
                    mma_bf16(acc[fm][fn], ah + 4*fm, bb + 2*fn);
            // pass 2: Alo * Bhi
            #pragma unroll
            for (int fm = 0; fm < 2; fm++)
                #pragma unroll
                for (int fn = 0; fn < 8; fn++)
                    mma_bf16(acc[fm][fn], al + 4*fm, bb + 2*fn);
            // ---- overwrite with Blo fragments ----
            #pragma unroll
            for (int p = 0; p < 4; p++) ldsm_x4(bb + 4*p, st + 3*MAT_B + boff[p]);
            // pass 3: Ahi * Blo
            #pragma unroll
            for (int fm = 0; fm < 2; fm++)
                #pragma unroll
                for (int fn = 0; fn < 8; fn++)
                    mma_bf16(acc[fm][fn], ah + 4*fm, bb + 2*fn);
        }
        __syncthreads();
    }

    // ---- epilogue: acc + bias -> C ----
    #pragma unroll
    for (int fm = 0; fm < 2; fm++) {
        const int row = bm*GBM + wm*32 + fm*16 + (lane >> 2);
        #pragma unroll
        for (int fn = 0; fn < 8; fn++) {
            const int col = bn*GBN + wn*64 + fn*8 + (lane & 3)*2;
            const float2 bv = *reinterpret_cast<const float2*>(bias + col);
            float2 o0, o1;
            o0.x = acc[fm][fn][0] + bv.x; o0.y = acc[fm][fn][1] + bv.y;
            o1.x = acc[fm][fn][2] + bv.x; o1.y = acc[fm][fn][3] + bv.y;
            *reinterpret_cast<float2*>(C + (size_t)row     * Ndim + col) = o0;
            *reinterpret_cast<float2*>(C + (size_t)(row+8) * Ndim + col) = o1;
        }
    }
}

// ---------------- persistent scan: 128 CTAs x 128 thr, 2 cols/warp ---------
#define SCAN_BLOCKS 128
#define SCAN_THREADS 128

__device__ __forceinline__ void grid_barrier(int nb) {
    __syncthreads();
    if (threadIdx.x == 0) {
        unsigned g = *((volatile unsigned*)&g_bar_gen);
        __threadfence();
        if (atomicAdd(&g_bar_count, 1) == (unsigned)(nb - 1)) {
            g_bar_count = 0;
            __threadfence();
            *((volatile unsigned*)&g_bar_gen) = g + 1;
        } else {
            while (*((volatile unsigned*)&g_bar_gen) == g) { __nanosleep(32); }
        }
        __threadfence();
    }
    __syncthreads();
}

__global__ __launch_bounds__(SCAN_THREADS)
void scan_kernel(const float* __restrict__ Whh, float* __restrict__ hfinal) {
    __shared__ __align__(16) float hsh[B_*H_];   // 32 KB
    const int tid  = threadIdx.x;
    const int warp = tid >> 5;                   // 0..3
    const int lane = tid & 31;
    const int j0   = blockIdx.x * 8 + warp * 2;  // two adjacent columns per warp
    const int j1   = j0 + 1;

    // Two W_hh rows stay in registers, packed as f32x2 pairs.
    unsigned long long w0[16], w1[16];
    {
        const float4* r0 = reinterpret_cast<const float4*>(Whh + (size_t)j0 * H_);
        const float4* r1 = reinterpret_cast<const float4*>(Whh + (size_t)j1 * H_);
        #pragma unroll
        for (int i = 0; i < 8; i++) {
            float4 a = r0[lane + 32*i];
            float4 b = r1[lane + 32*i];
            w0[2*i]   = pk2(a.x, a.y); w0[2*i+1] = pk2(a.z, a.w);
            w1[2*i]   = pk2(b.x, b.y); w1[2*i+1] = pk2(b.z, b.w);
        }
    }

    // zero h buffer 0
    {
        int idx = blockIdx.x*SCAN_THREADS + tid;
        if (idx < B_*H_) g_h[idx] = 0.f;
    }
    grid_barrier(SCAN_BLOCKS);

    for (int t = 0; t < T_; t++) {
        const int rp = t & 1, wp = rp ^ 1;
        // stage current h into shared (2048 float4 over 128 threads)
        float4* hs4 = reinterpret_cast<float4*>(hsh);
        const float4* hg4 = reinterpret_cast<const float4*>(g_h + rp*B_*H_);
        #pragma unroll
        for (int i = 0; i < (B_*H_/4)/SCAN_THREADS; i++)
            hs4[tid + SCAN_THREADS*i] = hg4[tid + SCAN_THREADS*i];
        __syncthreads();

        unsigned long long a0[B_], a1[B_];
        #pragma unroll
        for (int b = 0; b < B_; b++) { a0[b] = 0ull; a1[b] = 0ull; }
        #pragma unroll
        for (int i = 0; i < 8; i++) {
            const unsigned long long wl0 = w0[2*i], wh0 = w0[2*i+1];
            const unsigned long long wl1 = w1[2*i], wh1 = w1[2*i+1];
            #pragma unroll
            for (int b = 0; b < B_; b++) {
                const float4 hv = *reinterpret_cast<const float4*>(&hsh[b*H_ + lane*4 + 128*i]);
                const unsigned long long hl = pk2(hv.x, hv.y);
                const unsigned long long hh = pk2(hv.z, hv.w);
                ffma2(a0[b], wl0, hl); ffma2(a0[b], wh0, hh);
                ffma2(a1[b], wl1, hl); ffma2(a1[b], wh1, hh);
            }
        }
        // butterfly-reduce both column accumulators (all lanes get results)
        float s0[B_], s1[B_];
        #pragma unroll
        for (int b = 0; b < B_; b++) {
            float v0 = upk_sum(a0[b]), v1 = upk_sum(a1[b]);
            #pragma unroll
            for (int off = 16; off; off >>= 1) {
                v0 += __shfl_xor_sync(0xffffffffu, v0, off);
                v1 += __shfl_xor_sync(0xffffffffu, v1, off);
            }
            s0[b] = v0; s1[b] = v1;
        }
        // lanes 0-7 write column j0 (batch=lane); lanes 8-15 write j1
        if (lane < 16) {
            const int b = lane & 7;
            float va = s0[0], vb = s1[0];
            if (b == 1) { va = s0[1]; vb = s1[1]; }
            if (b == 2) { va = s0[2]; vb = s1[2]; }
            if (b == 3) { va = s0[3]; vb = s1[3]; }
            if (b == 4) { va = s0[4]; vb = s1[4]; }
            if (b == 5) { va = s0[5]; vb = s1[5]; }
            if (b == 6) { va = s0[6]; vb = s1[6]; }
            if (b == 7) { va = s0[7]; vb = s1[7]; }
            const float a = (lane < 8) ? va : vb;
            const int   j = (lane < 8) ? j0 : j1;
            const float hn = tanhf(a + g_pre[(size_t)b*(T_*H_) + t*H_ + j]);
            g_h[wp*B_*H_ + b*H_ + j] = hn;
            g_hs[(size_t)b*(T_*H_) + t*H_ + j] = hn;
            if (t == T_-1) hfinal[b*H_ + j] = hn;
        }
        __threadfence();
        grid_barrier(SCAN_BLOCKS);
    }
}

// ---------------- launch ----------------------------------------------------
extern "C" void kernel_launch(void* const* d_in, const int* in_sizes, int n_in,
                              void* d_out, int out_size) {
    const int*   x     = (const int*)  d_in[0];
    const float* embed = (const float*)d_in[1];
    const float* W_ih  = (const float*)d_in[2];
    const float* b_ih  = (const float*)d_in[3];
    const float* W_hh  = (const float*)d_in[4];
    const float* b_hh  = (const float*)d_in[5];
    const float* W_out = (const float*)d_in[6];
    const float* b_out = (const float*)d_in[7];
    float* out = (float*)d_out;

    void *p_Ahi, *p_Alo, *p_Wih_hi, *p_Wih_lo, *p_Wo_hi, *p_Wo_lo;
    void *p_Hhi, *p_Hlo, *p_pre, *p_hs, *p_bsum;
    cudaGetSymbolAddress(&p_Ahi, g_Ahi);       cudaGetSymbolAddress(&p_Alo, g_Alo);
    cudaGetSymbolAddress(&p_Wih_hi, g_Wih_hi); cudaGetSymbolAddress(&p_Wih_lo, g_Wih_lo);
    cudaGetSymbolAddress(&p_Wo_hi, g_Wo_hi);   cudaGetSymbolAddress(&p_Wo_lo, g_Wo_lo);
    cudaGetSymbolAddress(&p_Hhi, g_Hhi);       cudaGetSymbolAddress(&p_Hlo, g_Hlo);
    cudaGetSymbolAddress(&p_pre, g_pre);       cudaGetSymbolAddress(&p_hs, g_hs);
    cudaGetSymbolAddress(&p_bsum, g_bsum);

    cudaFuncSetAttribute(gemm_mma, cudaFuncAttributeMaxDynamicSharedMemorySize, SMEM_B);

    // 1) gather embeddings (split to bf16 hi/lo) + fused bias
    gather_kernel<<<M_ + 1, 256>>>(x, embed, b_ih, b_hh);

    // 2) split weights to bf16 hi/lo
    split_kernel<<<(H_*H_/4 + 255)/256, 256>>>(W_ih,
        (__nv_bfloat16*)p_Wih_hi, (__nv_bfloat16*)p_Wih_lo, (size_t)H_*H_);
    split_kernel<<<(int)(((size_t)V_*H_/4 + 255)/256), 256>>>(W_out,
        (__nv_bfloat16*)p_Wo_hi, (__nv_bfloat16*)p_Wo_lo, (size_t)V_*H_);

    // 3) pre = emb @ W_ih^T + (b_ih + b_hh)   [2048 x 1024]
    gemm_mma<<<dim3(M_/GBM, H_/GBN), 256, SMEM_B>>>(
        (const __nv_bfloat16*)p_Ahi, (const __nv_bfloat16*)p_Alo,
        (const __nv_bfloat16*)p_Wih_hi, (const __nv_bfloat16*)p_Wih_lo,
        (const float*)p_bsum, (float*)p_pre, H_);

    // 4) persistent recurrent scan; writes g_hs and h_final tail of d_out
    scan_kernel<<<SCAN_BLOCKS, SCAN_THREADS>>>(W_hh, out + (size_t)M_ * V_);

    // 5) split hidden states to bf16 hi/lo
    split_kernel<<<(M_*H_/4 + 255)/256, 256>>>((const float*)p_hs,
        (__nv_bfloat16*)p_Hhi, (__nv_bfloat16*)p_Hlo, (size_t)M_*H_);

    // 6) outputs = hs @ W_out^T + b_out   [2048 x 32000]
    gemm_mma<<<dim3(M_/GBM, V_/GBN), 256, SMEM_B>>>(
        (const __nv_bfloat16*)p_Hhi, (const __nv_bfloat16*)p_Hlo,
        (const __nv_bfloat16*)p_Wo_hi, (const __nv_bfloat16*)p_Wo_lo,
        b_out, out, V_);
}

// round 12
// speedup vs baseline: 1.3727x; 1.1760x over previous
#include <cuda_runtime.h>
#include <cuda_fp16.h>
#include <cstdint>
#include <cstring>

#define B_ 8
#define T_ 256
#define H_ 1024
#define V_ 32000
#define M_ (B_*T_)          // 2048 rows = (b,t)

// ---------------- scratch (device globals; no allocation allowed) ----------
__device__ __align__(16) __half g_Ahi[M_*H_];            // emb hi
__device__ __align__(16) __half g_Alo[M_*H_];            // emb lo
__device__ __align__(16) __half g_Wih[H_*H_];            // W_ih fp16
__device__ __align__(16) __half g_Wo[(size_t)V_*H_];     // W_out fp16
__device__ __align__(16) __half g_Hhi[M_*H_];            // hs hi
__device__ __align__(16) __half g_Hlo[M_*H_];            // hs lo
__device__ __align__(16) float g_pre[M_*H_];   // x_t @ W_ih^T + b_ih + b_hh
__device__ __align__(16) float g_hs [M_*H_];   // hidden states [b][t][j]
__device__ __align__(16) float g_h  [2*B_*H_]; // double-buffered current h
__device__ float g_bsum[H_];
__device__ unsigned g_bar_count;
__device__ unsigned g_bar_gen;

// ---------------- PTX helpers (arch-neutral: ldmatrix/mma/cp.async) --------
__device__ __forceinline__ uint32_t smem_to_u32(const void* p) {
    uint32_t a;
    asm("{ .reg .u64 t; cvta.to.shared.u64 t, %1; cvt.u32.u64 %0, t; }"
        : "=r"(a) : "l"(p));
    return a;
}
__device__ __forceinline__ void ldsm_x4(uint32_t* r, uint32_t addr) {
    asm volatile("ldmatrix.sync.aligned.m8n8.x4.shared.b16 {%0,%1,%2,%3}, [%4];"
        : "=r"(r[0]), "=r"(r[1]), "=r"(r[2]), "=r"(r[3]) : "r"(addr));
}
__device__ __forceinline__ void mma_f16(float* d, const uint32_t* a, const uint32_t* b) {
    asm volatile(
        "mma.sync.aligned.m16n8k16.row.col.f32.f16.f16.f32 "
        "{%0,%1,%2,%3}, {%4,%5,%6,%7}, {%8,%9}, {%0,%1,%2,%3};"
        : "+f"(d[0]), "+f"(d[1]), "+f"(d[2]), "+f"(d[3])
        : "r"(a[0]), "r"(a[1]), "r"(a[2]), "r"(a[3]), "r"(b[0]), "r"(b[1]));
}
__device__ __forceinline__ void cp16(uint32_t saddr, const void* g) {
    asm volatile("cp.async.cg.shared.global [%0], [%1], 16;" :: "r"(saddr), "l"(g));
}
#define CP_COMMIT() asm volatile("cp.async.commit_group;" ::: "memory")
#define CP_WAIT0()  asm volatile("cp.async.wait_group 0;" ::: "memory")
#define CP_WAIT1()  asm volatile("cp.async.wait_group 1;" ::: "memory")

// packed fp32x2 FMA (verified working on this toolchain)
__device__ __forceinline__ void ffma2(unsigned long long &c,
                                      unsigned long long a,
                                      unsigned long long b) {
    asm("fma.rn.f32x2 %0, %1, %2, %0;" : "+l"(c) : "l"(a), "l"(b));
}
__device__ __forceinline__ unsigned long long pk2(float x, float y) {
    float2 t; t.x = x; t.y = y;
    unsigned long long r; memcpy(&r, &t, 8); return r;
}
__device__ __forceinline__ float upk_sum(unsigned long long v) {
    float2 t; memcpy(&t, &v, 8); return t.x + t.y;
}

// ---------------- gather: emb rows split to fp16 hi/lo + fused bias --------
__global__ void gather_kernel(const int* __restrict__ x,
                              const float* __restrict__ embed,
                              const float* __restrict__ b_ih,
                              const float* __restrict__ b_hh) {
    int m = blockIdx.x;
    if (m < M_) {
        int tok = x[m];
        for (int i = threadIdx.x; i < H_; i += blockDim.x) {
            float v = embed[(size_t)tok * H_ + i];
            __half h = __float2half_rn(v);
            g_Ahi[(size_t)m * H_ + i] = h;
            g_Alo[(size_t)m * H_ + i] = __float2half_rn(v - __half2float(h));
        }
    } else {
        for (int i = threadIdx.x; i < H_; i += blockDim.x)
            g_bsum[i] = b_ih[i] + b_hh[i];
    }
}

// ---------------- fp32 -> fp16 hi/lo split (A operand) ---------------------
__global__ void split_hl_kernel(const float* __restrict__ src,
                                __half* __restrict__ hi,
                                __half* __restrict__ lo, size_t n) {
    size_t i = ((size_t)blockIdx.x * blockDim.x + threadIdx.x) * 4;
    if (i < n) {
        float4 v = *reinterpret_cast<const float4*>(src + i);
        __half h0 = __float2half_rn(v.x), h1 = __float2half_rn(v.y);
        __half h2 = __float2half_rn(v.z), h3 = __float2half_rn(v.w);
        __half2 hh0 = {h0, h1}, hh1 = {h2, h3};
        __half2 ll0 = {__float2half_rn(v.x - __half2float(h0)),
                       __float2half_rn(v.y - __half2float(h1))};
        __half2 ll1 = {__float2half_rn(v.z - __half2float(h2)),
                       __float2half_rn(v.w - __half2float(h3))};
        *reinterpret_cast<__half2*>(hi + i)     = hh0;
        *reinterpret_cast<__half2*>(hi + i + 2) = hh1;
        *reinterpret_cast<__half2*>(lo + i)     = ll0;
        *reinterpret_cast<__half2*>(lo + i + 2) = ll1;
    }
}

// ---------------- fp32 -> fp16 (B operand, hi only) ------------------------
__global__ void conv_h_kernel(const float* __restrict__ src,
                              __half* __restrict__ dst, size_t n) {
    size_t i = ((size_t)blockIdx.x * blockDim.x + threadIdx.x) * 4;
    if (i < n) {
        float4 v = *reinterpret_cast<const float4*>(src + i);
        __half2 a = {__float2half_rn(v.x), __float2half_rn(v.y)};
        __half2 b = {__float2half_rn(v.z), __float2half_rn(v.w)};
        *reinterpret_cast<__half2*>(dst + i)     = a;
        *reinterpret_cast<__half2*>(dst + i + 2) = b;
    }
}

// ---------------- split-fp16 HMMA GEMM (2-pass: (Ahi+Alo)*B) ---------------
// C[r][c] = sum_k A[r][k]*B[c][k] + bias[c];  B quantized to fp16 (2^-12).
// A: [Mrows][H_] row-major, B: [Ncols][H_] row-major.  K = H_ = 1024 fixed.
#define GBM 128
#define GBN 128
#define GBK 32
#define NKC (H_/GBK)                    // 32 k-chunks
#define LDT 40                          // smem row stride in fp16 (pad 8)
#define MAT_B (GBM*LDT*2)               // 10240 bytes per matrix tile
#define STAGE_B (3*MAT_B)               // 30720 bytes per stage (Ahi,Alo,B)
#define SMEM_B (2*STAGE_B)              // 61440 bytes total

__global__ __launch_bounds__(256, 2)
void gemm_mma(const __half* __restrict__ Ahi, const __half* __restrict__ Alo,
              const __half* __restrict__ Bh,
              const float* __restrict__ bias, float* __restrict__ C, int Ndim) {
    extern __shared__ __align__(16) char sm[];
    const uint32_t sb = smem_to_u32(sm);
    const int tid  = threadIdx.x;
    const int lane = tid & 31, wid = tid >> 5;
    const int wm = wid & 3, wn = wid >> 2;      // warp tile: rows 32*wm, cols 64*wn
    const int bm = blockIdx.x, bn = blockIdx.y;

    // ---- prefetch chunk c into stage c&1 (6 x cp.async.16B per thread) ----
    auto prefetch = [&](int c) {
        const uint32_t st = sb + (uint32_t)(c & 1) * STAGE_B;
        const int kcol = c * GBK;
        #pragma unroll
        for (int q = 0; q < 2; q++) {
            const int u = tid + 256*q;
            const int r = u >> 2, sg = u & 3;
            const uint32_t so = (uint32_t)(r*LDT + sg*8) * 2;
            const size_t goA = (size_t)(bm*GBM + r) * H_ + kcol + sg*8;
            const size_t goB = (size_t)(bn*GBN + r) * H_ + kcol + sg*8;
            cp16(st + 0*MAT_B + so, Ahi + goA);
            cp16(st + 1*MAT_B + so, Alo + goA);
            cp16(st + 2*MAT_B + so, Bh  + goB);
        }
    };

    float acc[2][8][4];
    #pragma unroll
    for (int i = 0; i < 2; i++)
        #pragma unroll
        for (int j = 0; j < 8; j++)
            #pragma unroll
            for (int q = 0; q < 4; q++) acc[i][j][q] = 0.f;

    prefetch(0); CP_COMMIT();

    for (int c = 0; c < NKC; c++) {
        if (c + 1 < NKC) { prefetch(c + 1); CP_COMMIT(); CP_WAIT1(); }
        else             { CP_WAIT0(); }
        __syncthreads();

        const uint32_t st = sb + (uint32_t)(c & 1) * STAGE_B;
        #pragma unroll
        for (int ks = 0; ks < 2; ks++) {
            // A fragments (hi & lo): rows wm*32 + f*16 + lane%16
            uint32_t ah[8], al[8];
            #pragma unroll
            for (int f = 0; f < 2; f++) {
                const int row = wm*32 + f*16 + (lane & 15);
                const uint32_t off = (uint32_t)(row*LDT + ks*16 + (lane >> 4)*8) * 2;
                ldsm_x4(ah + 4*f, st + 0*MAT_B + off);
                ldsm_x4(al + 4*f, st + 1*MAT_B + off);
            }
            // B fragments
            uint32_t bb[16];
            #pragma unroll
            for (int p = 0; p < 4; p++) {
                const int n  = wn*64 + p*16 + ((lane >> 4) << 3) + (lane & 7);
                const int kc = ks*16 + ((lane >> 3) & 1) * 8;
                const uint32_t off = (uint32_t)(n*LDT + kc) * 2;
                ldsm_x4(bb + 4*p, st + 2*MAT_B + off);
            }
            // pass 1: Ahi * B
            #pragma unroll
            for (int fm = 0; fm < 2; fm++)
                #pragma unroll
                for (int fn = 0; fn < 8; fn++)
                    mma_f16(acc[fm][fn], ah + 4*fm, bb + 2*fn);
            // pass 2: Alo * B
            #pragma unroll
            for (int fm = 0; fm < 2; fm++)
                #pragma unroll
                for (int fn = 0; fn < 8; fn++)
                    mma_f16(acc[fm][fn], al + 4*fm, bb + 2*fn);
        }
        __syncthreads();
    }

    // ---- epilogue: acc + bias -> C ----
    #pragma unroll
    for (int fm = 0; fm < 2; fm++) {
        const int row = bm*GBM + wm*32 + fm*16 + (lane >> 2);
        #pragma unroll
        for (int fn = 0; fn < 8; fn++) {
            const int col = bn*GBN + wn*64 + fn*8 + (lane & 3)*2;
            const float2 bv = *reinterpret_cast<const float2*>(bias + col);
            float2 o0, o1;
            o0.x = acc[fm][fn][0] + bv.x; o0.y = acc[fm][fn][1] + bv.y;
            o1.x = acc[fm][fn][2] + bv.x; o1.y = acc[fm][fn][3] + bv.y;
            *reinterpret_cast<float2*>(C + (size_t)row     * Ndim + col) = o0;
            *reinterpret_cast<float2*>(C + (size_t)(row+8) * Ndim + col) = o1;
        }
    }
}

// ---------------- persistent scan: 128 CTAs x 128 thr, 2 cols/warp ---------
#define SCAN_BLOCKS 128
#define SCAN_THREADS 128

__device__ __forceinline__ void grid_barrier(int nb) {
    __syncthreads();
    if (threadIdx.x == 0) {
        unsigned g = *((volatile unsigned*)&g_bar_gen);
        __threadfence();
        if (atomicAdd(&g_bar_count, 1) == (unsigned)(nb - 1)) {
            g_bar_count = 0;
            __threadfence();
            *((volatile unsigned*)&g_bar_gen) = g + 1;
        } else {
            while (*((volatile unsigned*)&g_bar_gen) == g) { __nanosleep(32); }
        }
        __threadfence();
    }
    __syncthreads();
}

__global__ __launch_bounds__(SCAN_THREADS)
void scan_kernel(const float* __restrict__ Whh, float* __restrict__ hfinal) {
    __shared__ __align__(16) float hsh[B_*H_];   // 32 KB
    const int tid  = threadIdx.x;
    const int warp = tid >> 5;                   // 0..3
    const int lane = tid & 31;
    const int j0   = blockIdx.x * 8 + warp * 2;  // two adjacent columns per warp
    const int j1   = j0 + 1;

    // Two W_hh rows stay in registers, packed as f32x2 pairs.
    unsigned long long w0[16], w1[16];
    {
        const float4* r0 = reinterpret_cast<const float4*>(Whh + (size_t)j0 * H_);
        const float4* r1 = reinterpret_cast<const float4*>(Whh + (size_t)j1 * H_);
        #pragma unroll
        for (int i = 0; i < 8; i++) {
            float4 a = r0[lane + 32*i];
            float4 b = r1[lane + 32*i];
            w0[2*i]   = pk2(a.x, a.y); w0[2*i+1] = pk2(a.z, a.w);
            w1[2*i]   = pk2(b.x, b.y); w1[2*i+1] = pk2(b.z, b.w);
        }
    }

    // zero h buffer 0
    {
        int idx = blockIdx.x*SCAN_THREADS + tid;
        if (idx < B_*H_) g_h[idx] = 0.f;
    }
    grid_barrier(SCAN_BLOCKS);

    for (int t = 0; t < T_; t++) {
        const int rp = t & 1, wp = rp ^ 1;
        // stage current h into shared (2048 float4 over 128 threads)
        float4* hs4 = reinterpret_cast<float4*>(hsh);
        const float4* hg4 = reinterpret_cast<const float4*>(g_h + rp*B_*H_);
        #pragma unroll
        for (int i = 0; i < (B_*H_/4)/SCAN_THREADS; i++)
            hs4[tid + SCAN_THREADS*i] = hg4[tid + SCAN_THREADS*i];
        __syncthreads();

        unsigned long long a0[B_], a1[B_];
        #pragma unroll
        for (int b = 0; b < B_; b++) { a0[b] = 0ull; a1[b] = 0ull; }
        #pragma unroll
        for (int i = 0; i < 8; i++) {
            const unsigned long long wl0 = w0[2*i], wh0 = w0[2*i+1];
            const unsigned long long wl1 = w1[2*i], wh1 = w1[2*i+1];
            #pragma unroll
            for (int b = 0; b < B_; b++) {
                const float4 hv = *reinterpret_cast<const float4*>(&hsh[b*H_ + lane*4 + 128*i]);
                const unsigned long long hl = pk2(hv.x, hv.y);
                const unsigned long long hh = pk2(hv.z, hv.w);
                ffma2(a0[b], wl0, hl); ffma2(a0[b], wh0, hh);
                ffma2(a1[b], wl1, hl); ffma2(a1[b], wh1, hh);
            }
        }
        // butterfly-reduce both column accumulators (all lanes get results)
        float s0[B_], s1[B_];
        #pragma unroll
        for (int b = 0; b < B_; b++) {
            float v0 = upk_sum(a0[b]), v1 = upk_sum(a1[b]);
            #pragma unroll
            for (int off = 16; off; off >>= 1) {
                v0 += __shfl_xor_sync(0xffffffffu, v0, off);
                v1 += __shfl_xor_sync(0xffffffffu, v1, off);
            }
            s0[b] = v0; s1[b] = v1;
        }
        // lanes 0-7 write column j0 (batch=lane); lanes 8-15 write j1
        if (lane < 16) {
            const int b = lane & 7;
            float va = s0[0], vb = s1[0];
            if (b == 1) { va = s0[1]; vb = s1[1]; }
            if (b == 2) { va = s0[2]; vb = s1[2]; }
            if (b == 3) { va = s0[3]; vb = s1[3]; }
            if (b == 4) { va = s0[4]; vb = s1[4]; }
            if (b == 5) { va = s0[5]; vb = s1[5]; }
            if (b == 6) { va = s0[6]; vb = s1[6]; }
            if (b == 7) { va = s0[7]; vb = s1[7]; }
            const float a = (lane < 8) ? va : vb;
            const int   j = (lane < 8) ? j0 : j1;
            const float hn = tanhf(a + g_pre[(size_t)b*(T_*H_) + t*H_ + j]);
            g_h[wp*B_*H_ + b*H_ + j] = hn;
            g_hs[(size_t)b*(T_*H_) + t*H_ + j] = hn;
            if (t == T_-1) hfinal[b*H_ + j] = hn;
        }
        __threadfence();
        grid_barrier(SCAN_BLOCKS);
    }
}

// ---------------- launch ----------------------------------------------------
extern "C" void kernel_launch(void* const* d_in, const int* in_sizes, int n_in,
                              void* d_out, int out_size) {
    const int*   x     = (const int*)  d_in[0];
    const float* embed = (const float*)d_in[1];
    const float* W_ih  = (const float*)d_in[2];
    const float* b_ih  = (const float*)d_in[3];
    const float* W_hh  = (const float*)d_in[4];
    const float* b_hh  = (const float*)d_in[5];
    const float* W_out = (const float*)d_in[6];
    const float* b_out = (const float*)d_in[7];
    float* out = (float*)d_out;

    void *p_Ahi, *p_Alo, *p_Wih, *p_Wo, *p_Hhi, *p_Hlo, *p_pre, *p_hs, *p_bsum;
    cudaGetSymbolAddress(&p_Ahi, g_Ahi);   cudaGetSymbolAddress(&p_Alo, g_Alo);
    cudaGetSymbolAddress(&p_Wih, g_Wih);   cudaGetSymbolAddress(&p_Wo, g_Wo);
    cudaGetSymbolAddress(&p_Hhi, g_Hhi);   cudaGetSymbolAddress(&p_Hlo, g_Hlo);
    cudaGetSymbolAddress(&p_pre, g_pre);   cudaGetSymbolAddress(&p_hs, g_hs);
    cudaGetSymbolAddress(&p_bsum, g_bsum);

    cudaFuncSetAttribute(gemm_mma, cudaFuncAttributeMaxDynamicSharedMemorySize, SMEM_B);

    // 1) gather embeddings (split to fp16 hi/lo) + fused bias
    gather_kernel<<<M_ + 1, 256>>>(x, embed, b_ih, b_hh);

    // 2) convert weights to fp16 (B operand: single quantization, 2^-12)
    conv_h_kernel<<<(H_*H_/4 + 255)/256, 256>>>(W_ih, (__half*)p_Wih, (size_t)H_*H_);
    conv_h_kernel<<<(int)(((size_t)V_*H_/4 + 255)/256), 256>>>(W_out, (__half*)p_Wo, (size_t)V_*H_);

    // 3) pre = emb @ W_ih^T + (b_ih + b_hh)   [2048 x 1024]
    gemm_mma<<<dim3(M_/GBM, H_/GBN), 256, SMEM_B>>>(
        (const __half*)p_Ahi, (const __half*)p_Alo, (const __half*)p_Wih,
        (const float*)p_bsum, (float*)p_pre, H_);

    // 4) persistent recurrent scan; writes g_hs and h_final tail of d_out
    scan_kernel<<<SCAN_BLOCKS, SCAN_THREADS>>>(W_hh, out + (size_t)M_ * V_);

    // 5) split hidden states to fp16 hi/lo (A operand of output GEMM)
    split_hl_kernel<<<(M_*H_/4 + 255)/256, 256>>>((const float*)p_hs,
        (__half*)p_Hhi, (__half*)p_Hlo, (size_t)M_*H_);

    // 6) outputs = hs @ W_out^T + b_out   [2048 x 32000]
    gemm_mma<<<dim3(M_/GBM, V_/GBN), 256, SMEM_B>>>(
        (const __half*)p_Hhi, (const __half*)p_Hlo, (const __half*)p_Wo,
        b_out, out, V_);
}

// round 13
// speedup vs baseline: 1.6415x; 1.1958x over previous
#include <cuda_runtime.h>
#include <cuda_fp16.h>
#include <cstdint>
#include <cstring>

#define B_ 8
#define T_ 256
#define H_ 1024
#define V_ 32000
#define M_ (B_*T_)          // 2048 rows = (b,t)

// ---------------- scratch (device globals; no allocation allowed) ----------
__device__ __align__(16) __half g_Ahi[M_*H_];            // emb hi
__device__ __align__(16) __half g_Alo[M_*H_];            // emb lo
__device__ __align__(16) __half g_Wih[H_*H_];            // W_ih fp16
__device__ __align__(16) __half g_Wo[(size_t)V_*H_];     // W_out fp16
__device__ __align__(16) __half g_Hhi[M_*H_];            // hs hi
__device__ __align__(16) __half g_Hlo[M_*H_];            // hs lo
__device__ __align__(16) float g_pre[M_*H_];   // x_t @ W_ih^T + b_ih + b_hh
__device__ __align__(16) float g_hs [M_*H_];   // hidden states [b][t][j]
__device__ __align__(16) float g_h  [2*B_*H_]; // double-buffered current h
__device__ float g_bsum[H_];
__device__ unsigned g_bar_count;

// ---------------- PTX helpers (arch-neutral: ldmatrix/mma/cp.async) --------
__device__ __forceinline__ uint32_t smem_to_u32(const void* p) {
    uint32_t a;
    asm("{ .reg .u64 t; cvta.to.shared.u64 t, %1; cvt.u32.u64 %0, t; }"
        : "=r"(a) : "l"(p));
    return a;
}
__device__ __forceinline__ void ldsm_x4(uint32_t* r, uint32_t addr) {
    asm volatile("ldmatrix.sync.aligned.m8n8.x4.shared.b16 {%0,%1,%2,%3}, [%4];"
        : "=r"(r[0]), "=r"(r[1]), "=r"(r[2]), "=r"(r[3]) : "r"(addr));
}
__device__ __forceinline__ void mma_f16(float* d, const uint32_t* a, const uint32_t* b) {
    asm volatile(
        "mma.sync.aligned.m16n8k16.row.col.f32.f16.f16.f32 "
        "{%0,%1,%2,%3}, {%4,%5,%6,%7}, {%8,%9}, {%0,%1,%2,%3};"
        : "+f"(d[0]), "+f"(d[1]), "+f"(d[2]), "+f"(d[3])
        : "r"(a[0]), "r"(a[1]), "r"(a[2]), "r"(a[3]), "r"(b[0]), "r"(b[1]));
}
__device__ __forceinline__ void cp16(uint32_t saddr, const void* g) {
    asm volatile("cp.async.cg.shared.global [%0], [%1], 16;" :: "r"(saddr), "l"(g));
}
#define CP_COMMIT() asm volatile("cp.async.commit_group;" ::: "memory")
#define CP_WAIT0()  asm volatile("cp.async.wait_group 0;" ::: "memory")
#define CP_WAIT1()  asm volatile("cp.async.wait_group 1;" ::: "memory")

// packed fp32x2 FMA (verified working on this toolchain)
__device__ __forceinline__ void ffma2(unsigned long long &c,
                                      unsigned long long a,
                                      unsigned long long b) {
    asm("fma.rn.f32x2 %0, %1, %2, %0;" : "+l"(c) : "l"(a), "l"(b));
}
__device__ __forceinline__ unsigned long long pk2(float x, float y) {
    float2 t; t.x = x; t.y = y;
    unsigned long long r; memcpy(&r, &t, 8); return r;
}
__device__ __forceinline__ float upk_sum(unsigned long long v) {
    float2 t; memcpy(&t, &v, 8); return t.x + t.y;
}

// ---------------- gather: emb rows split to fp16 hi/lo + fused bias --------
__global__ void gather_kernel(const int* __restrict__ x,
                              const float* __restrict__ embed,
                              const float* __restrict__ b_ih,
                              const float* __restrict__ b_hh) {
    int m = blockIdx.x;
    if (m < M_) {
        int tok = x[m];
        for (int i = threadIdx.x; i < H_; i += blockDim.x) {
            float v = embed[(size_t)tok * H_ + i];
            __half h = __float2half_rn(v);
            g_Ahi[(size_t)m * H_ + i] = h;
            g_Alo[(size_t)m * H_ + i] = __float2half_rn(v - __half2float(h));
        }
    } else {
        // also reset the scan's monotonic grid-barrier counter (stream order
        // guarantees this lands before scan_kernel starts, every replay)
        if (threadIdx.x == 0) g_bar_count = 0;
        for (int i = threadIdx.x; i < H_; i += blockDim.x)
            g_bsum[i] = b_ih[i] + b_hh[i];
    }
}

// ---------------- fp32 -> fp16 hi/lo split (A operand) ---------------------
__global__ void split_hl_kernel(const float* __restrict__ src,
                                __half* __restrict__ hi,
                                __half* __restrict__ lo, size_t n) {
    size_t i = ((size_t)blockIdx.x * blockDim.x + threadIdx.x) * 4;
    if (i < n) {
        float4 v = *reinterpret_cast<const float4*>(src + i);
        __half h0 = __float2half_rn(v.x), h1 = __float2half_rn(v.y);
        __half h2 = __float2half_rn(v.z), h3 = __float2half_rn(v.w);
        __half2 hh0 = {h0, h1}, hh1 = {h2, h3};
        __half2 ll0 = {__float2half_rn(v.x - __half2float(h0)),
                       __float2half_rn(v.y - __half2float(h1))};
        __half2 ll1 = {__float2half_rn(v.z - __half2float(h2)),
                       __float2half_rn(v.w - __half2float(h3))};
        *reinterpret_cast<__half2*>(hi + i)     = hh0;
        *reinterpret_cast<__half2*>(hi + i + 2) = hh1;
        *reinterpret_cast<__half2*>(lo + i)     = ll0;
        *reinterpret_cast<__half2*>(lo + i + 2) = ll1;
    }
}

// ---------------- fp32 -> fp16 (B operand, hi only) ------------------------
__global__ void conv_h_kernel(const float* __restrict__ src,
                              __half* __restrict__ dst, size_t n) {
    size_t i = ((size_t)blockIdx.x * blockDim.x + threadIdx.x) * 4;
    if (i < n) {
        float4 v = *reinterpret_cast<const float4*>(src + i);
        __half2 a = {__float2half_rn(v.x), __float2half_rn(v.y)};
        __half2 b = {__float2half_rn(v.z), __float2half_rn(v.w)};
        *reinterpret_cast<__half2*>(dst + i)     = a;
        *reinterpret_cast<__half2*>(dst + i + 2) = b;
    }
}

// ---------------- split-fp16 HMMA GEMM (2-pass: (Ahi+Alo)*B) ---------------
// C[r][c] = sum_k A[r][k]*B[c][k] + bias[c];  B quantized to fp16 (2^-12).
// A: [Mrows][H_] row-major, B: [Ncols][H_] row-major.  K = H_ = 1024 fixed.
#define GBM 128
#define GBN 128
#define GBK 32
#define NKC (H_/GBK)                    // 32 k-chunks
#define LDT 40                          // smem row stride in fp16 (pad 8)
#define MAT_B (GBM*LDT*2)               // 10240 bytes per matrix tile
#define STAGE_B (3*MAT_B)               // 30720 bytes per stage (Ahi,Alo,B)
#define SMEM_B (2*STAGE_B)              // 61440 bytes total

__global__ __launch_bounds__(256, 2)
void gemm_mma(const __half* __restrict__ Ahi, const __half* __restrict__ Alo,
              const __half* __restrict__ Bh,
              const float* __restrict__ bias, float* __restrict__ C, int Ndim) {
    extern __shared__ __align__(16) char sm[];
    const uint32_t sb = smem_to_u32(sm);
    const int tid  = threadIdx.x;
    const int lane = tid & 31, wid = tid >> 5;
    const int wm = wid & 3, wn = wid >> 2;      // warp tile: rows 32*wm, cols 64*wn
    const int bm = blockIdx.x, bn = blockIdx.y;

    // ---- prefetch chunk c into stage c&1 (6 x cp.async.16B per thread) ----
    auto prefetch = [&](int c) {
        const uint32_t st = sb + (uint32_t)(c & 1) * STAGE_B;
        const int kcol = c * GBK;
        #pragma unroll
        for (int q = 0; q < 2; q++) {
            const int u = tid + 256*q;
            const int r = u >> 2, sg = u & 3;
            const uint32_t so = (uint32_t)(r*LDT + sg*8) * 2;
            const size_t goA = (size_t)(bm*GBM + r) * H_ + kcol + sg*8;
            const size_t goB = (size_t)(bn*GBN + r) * H_ + kcol + sg*8;
            cp16(st + 0*MAT_B + so, Ahi + goA);
            cp16(st + 1*MAT_B + so, Alo + goA);
            cp16(st + 2*MAT_B + so, Bh  + goB);
        }
    };

    float acc[2][8][4];
    #pragma unroll
    for (int i = 0; i < 2; i++)
        #pragma unroll
        for (int j = 0; j < 8; j++)
            #pragma unroll
            for (int q = 0; q < 4; q++) acc[i][j][q] = 0.f;

    prefetch(0); CP_COMMIT();

    for (int c = 0; c < NKC; c++) {
        if (c + 1 < NKC) { prefetch(c + 1); CP_COMMIT(); CP_WAIT1(); }
        else             { CP_WAIT0(); }
        __syncthreads();

        const uint32_t st = sb + (uint32_t)(c & 1) * STAGE_B;
        #pragma unroll
        for (int ks = 0; ks < 2; ks++) {
            // A fragments (hi & lo): rows wm*32 + f*16 + lane%16
            uint32_t ah[8], al[8];
            #pragma unroll
            for (int f = 0; f < 2; f++) {
                const int row = wm*32 + f*16 + (lane & 15);
                const uint32_t off = (uint32_t)(row*LDT + ks*16 + (lane >> 4)*8) * 2;
                ldsm_x4(ah + 4*f, st + 0*MAT_B + off);
                ldsm_x4(al + 4*f, st + 1*MAT_B + off);
            }
            // B fragments
            uint32_t bb[16];
            #pragma unroll
            for (int p = 0; p < 4; p++) {
                const int n  = wn*64 + p*16 + ((lane >> 4) << 3) + (lane & 7);
                const int kc = ks*16 + ((lane >> 3) & 1) * 8;
                const uint32_t off = (uint32_t)(n*LDT + kc) * 2;
                ldsm_x4(bb + 4*p, st + 2*MAT_B + off);
            }
            // pass 1: Ahi * B
            #pragma unroll
            for (int fm = 0; fm < 2; fm++)
                #pragma unroll
                for (int fn = 0; fn < 8; fn++)
                    mma_f16(acc[fm][fn], ah + 4*fm, bb + 2*fn);
            // pass 2: Alo * B
            #pragma unroll
            for (int fm = 0; fm < 2; fm++)
                #pragma unroll
                for (int fn = 0; fn < 8; fn++)
                    mma_f16(acc[fm][fn], al + 4*fm, bb + 2*fn);
        }
        __syncthreads();
    }

    // ---- epilogue: acc + bias -> C ----
    #pragma unroll
    for (int fm = 0; fm < 2; fm++) {
        const int row = bm*GBM + wm*32 + fm*16 + (lane >> 2);
        #pragma unroll
        for (int fn = 0; fn < 8; fn++) {
            const int col = bn*GBN + wn*64 + fn*8 + (lane & 3)*2;
            const float2 bv = *reinterpret_cast<const float2*>(bias + col);
            float2 o0, o1;
            o0.x = acc[fm][fn][0] + bv.x; o0.y = acc[fm][fn][1] + bv.y;
            o1.x = acc[fm][fn][2] + bv.x; o1.y = acc[fm][fn][3] + bv.y;
            *reinterpret_cast<float2*>(C + (size_t)row     * Ndim + col) = o0;
            *reinterpret_cast<float2*>(C + (size_t)(row+8) * Ndim + col) = o1;
        }
    }
}

// ---------------- persistent scan: 128 CTAs x 128 thr, 2 cols/warp ---------
// Grid barrier: monotonic counter, RED arrival, hot volatile poll, single
// release fence per CTA per step. h cross-step traffic is L1-bypassing
// (__stcg / __ldcg), so no acquire-side L1 invalidate is needed.
#define SCAN_BLOCKS 128
#define SCAN_THREADS 128

__device__ __forceinline__ void grid_barrier_t(unsigned target) {
    __syncthreads();
    if (threadIdx.x == 0) {
        __threadfence();                       // release: publish h writes to L2
        atomicAdd(&g_bar_count, 1);            // result unused -> REDG
        const volatile unsigned* c = (const volatile unsigned*)&g_bar_count;
        while (*c < target) { }                // hot poll (L2)
    }
    __syncthreads();                            // exec+compiler barrier for CTA
}

__global__ __launch_bounds__(SCAN_THREADS)
void scan_kernel(const float* __restrict__ Whh, float* __restrict__ hfinal) {
    __shared__ __align__(16) float hsh[B_*H_];   // 32 KB
    const int tid  = threadIdx.x;
    const int warp = tid >> 5;                   // 0..3
    const int lane = tid & 31;
    const int j0   = blockIdx.x * 8 + warp * 2;  // two adjacent columns per warp
    const int j1   = j0 + 1;

    // Two W_hh rows stay in registers, packed as f32x2 pairs.
    unsigned long long w0[16], w1[16];
    {
        const float4* r0 = reinterpret_cast<const float4*>(Whh + (size_t)j0 * H_);
        const float4* r1 = reinterpret_cast<const float4*>(Whh + (size_t)j1 * H_);
        #pragma unroll
        for (int i = 0; i < 8; i++) {
            float4 a = r0[lane + 32*i];
            float4 b = r1[lane + 32*i];
            w0[2*i]   = pk2(a.x, a.y); w0[2*i+1] = pk2(a.z, a.w);
            w1[2*i]   = pk2(b.x, b.y); w1[2*i+1] = pk2(b.z, b.w);
        }
    }

    // zero h buffer 0 (L2-resident stores)
    {
        int idx = blockIdx.x*SCAN_THREADS + tid;
        if (idx < B_*H_) __stcg(&g_h[idx], 0.f);
    }
    unsigned bar_k = 1;
    grid_barrier_t(bar_k * SCAN_BLOCKS); bar_k++;

    for (int t = 0; t < T_; t++) {
        const int rp = t & 1, wp = rp ^ 1;
        // stage current h into shared, bypassing L1 (coherence point = L2)
        float4* hs4 = reinterpret_cast<float4*>(hsh);
        const float4* hg4 = reinterpret_cast<const float4*>(g_h + rp*B_*H_);
        #pragma unroll
        for (int i = 0; i < (B_*H_/4)/SCAN_THREADS; i++)
            hs4[tid + SCAN_THREADS*i] = __ldcg(&hg4[tid + SCAN_THREADS*i]);
        __syncthreads();

        unsigned long long a0[B_], a1[B_];
        #pragma unroll
        for (int b = 0; b < B_; b++) { a0[b] = 0ull; a1[b] = 0ull; }
        #pragma unroll
        for (int i = 0; i < 8; i++) {
            const unsigned long long wl0 = w0[2*i], wh0 = w0[2*i+1];
            const unsigned long long wl1 = w1[2*i], wh1 = w1[2*i+1];
            #pragma unroll
            for (int b = 0; b < B_; b++) {
                const float4 hv = *reinterpret_cast<const float4*>(&hsh[b*H_ + lane*4 + 128*i]);
                const unsigned long long hl = pk2(hv.x, hv.y);
                const unsigned long long hh = pk2(hv.z, hv.w);
                ffma2(a0[b], wl0, hl); ffma2(a0[b], wh0, hh);
                ffma2(a1[b], wl1, hl); ffma2(a1[b], wh1, hh);
            }
        }
        // butterfly-reduce both column accumulators (all lanes get results)
        float s0[B_], s1[B_];
        #pragma unroll
        for (int b = 0; b < B_; b++) {
            float v0 = upk_sum(a0[b]), v1 = upk_sum(a1[b]);
            #pragma unroll
            for (int off = 16; off; off >>= 1) {
                v0 += __shfl_xor_sync(0xffffffffu, v0, off);
                v1 += __shfl_xor_sync(0xffffffffu, v1, off);
            }
            s0[b] = v0; s1[b] = v1;
        }
        // lanes 0-7 write column j0 (batch=lane); lanes 8-15 write j1
        if (lane < 16) {
            const int b = lane & 7;
            float va = s0[0], vb = s1[0];
            if (b == 1) { va = s0[1]; vb = s1[1]; }
            if (b == 2) { va = s0[2]; vb = s1[2]; }
            if (b == 3) { va = s0[3]; vb = s1[3]; }
            if (b == 4) { va = s0[4]; vb = s1[4]; }
            if (b == 5) { va = s0[5]; vb = s1[5]; }
            if (b == 6) { va = s0[6]; vb = s1[6]; }
            if (b == 7) { va = s0[7]; vb = s1[7]; }
            const float a = (lane < 8) ? va : vb;
            const int   j = (lane < 8) ? j0 : j1;
            const float hn = tanhf(a + g_pre[(size_t)b*(T_*H_) + t*H_ + j]);
            __stcg(&g_h[wp*B_*H_ + b*H_ + j], hn);
            g_hs[(size_t)b*(T_*H_) + t*H_ + j] = hn;
            if (t == T_-1) hfinal[b*H_ + j] = hn;
        }
        grid_barrier_t(bar_k * SCAN_BLOCKS); bar_k++;
    }
}

// ---------------- launch ----------------------------------------------------
extern "C" void kernel_launch(void* const* d_in, const int* in_sizes, int n_in,
                              void* d_out, int out_size) {
    const int*   x     = (const int*)  d_in[0];
    const float* embed = (const float*)d_in[1];
    const float* W_ih  = (const float*)d_in[2];
    const float* b_ih  = (const float*)d_in[3];
    const float* W_hh  = (const float*)d_in[4];
    const float* b_hh  = (const float*)d_in[5];
    const float* W_out = (const float*)d_in[6];
    const float* b_out = (const float*)d_in[7];
    float* out = (float*)d_out;

    void *p_Ahi, *p_Alo, *p_Wih, *p_Wo, *p_Hhi, *p_Hlo, *p_pre, *p_hs, *p_bsum;
    cudaGetSymbolAddress(&p_Ahi, g_Ahi);   cudaGetSymbolAddress(&p_Alo, g_Alo);
    cudaGetSymbolAddress(&p_Wih, g_Wih);   cudaGetSymbolAddress(&p_Wo, g_Wo);
    cudaGetSymbolAddress(&p_Hhi, g_Hhi);   cudaGetSymbolAddress(&p_Hlo, g_Hlo);
    cudaGetSymbolAddress(&p_pre, g_pre);   cudaGetSymbolAddress(&p_hs, g_hs);
    cudaGetSymbolAddress(&p_bsum, g_bsum);

    cudaFuncSetAttribute(gemm_mma, cudaFuncAttributeMaxDynamicSharedMemorySize, SMEM_B);

    // 1) gather embeddings (split to fp16 hi/lo) + fused bias + barrier reset
    gather_kernel<<<M_ + 1, 256>>>(x, embed, b_ih, b_hh);

    // 2) convert weights to fp16 (B operand: single quantization, 2^-12)
    conv_h_kernel<<<(H_*H_/4 + 255)/256, 256>>>(W_ih, (__half*)p_Wih, (size_t)H_*H_);
    conv_h_kernel<<<(int)(((size_t)V_*H_/4 + 255)/256), 256>>>(W_out, (__half*)p_Wo, (size_t)V_*H_);

    // 3) pre = emb @ W_ih^T + (b_ih + b_hh)   [2048 x 1024]
    gemm_mma<<<dim3(M_/GBM, H_/GBN), 256, SMEM_B>>>(
        (const __half*)p_Ahi, (const __half*)p_Alo, (const __half*)p_Wih,
        (const float*)p_bsum, (float*)p_pre, H_);

    // 4) persistent recurrent scan; writes g_hs and h_final tail of d_out
    scan_kernel<<<SCAN_BLOCKS, SCAN_THREADS>>>(W_hh, out + (size_t)M_ * V_);

    // 5) split hidden states to fp16 hi/lo (A operand of output GEMM)
    split_hl_kernel<<<(M_*H_/4 + 255)/256, 256>>>((const float*)p_hs,
        (__half*)p_Hhi, (__half*)p_Hlo, (size_t)M_*H_);

    // 6) outputs = hs @ W_out^T + b_out   [2048 x 32000]
    gemm_mma<<<dim3(M_/GBM, V_/GBN), 256, SMEM_B>>>(
        (const __half*)p_Hhi, (const __half*)p_Hlo, (const __half*)p_Wo,
        b_out, out, V_);
}